// round 1
// baseline (speedup 1.0000x reference)
#include <cuda_runtime.h>
#include <math_constants.h>

// Shapes (fixed by the problem)
#define Bq   2
#define Sq   2048
#define Dq   1024
#define Hq   16
#define DHq  64
#define BHq  (Bq*Hq)          // 32
#define Mq   (Bq*Sq)          // 4096 rows of X

// Scratch: Q,K,V in [B,H,S,DH]; ctx in [B,S,D]
__device__ float g_q  [BHq * Sq * DHq];
__device__ float g_k  [BHq * Sq * DHq];
__device__ float g_v  [BHq * Sq * DHq];
__device__ float g_ctx[Bq * Sq * Dq];

// ---------------------------------------------------------------------------
// SGEMM core: C[128x128] tile = A[M,K] * B[K,N], K=N=1024, BK=8,
// 256 threads, 8x8 microtile per thread.
// MODE 0: epilogue scatters into g_q/g_k/g_v ([B,H,S,DH]) selected by blockIdx.z
// MODE 1: epilogue writes d_out = acc + bias (plain row-major [4096,1024])
// ---------------------------------------------------------------------------
template <int MODE>
__global__ __launch_bounds__(256)
void gemm_kernel(const float* __restrict__ A,
                 const float* __restrict__ W0,
                 const float* __restrict__ W1,
                 const float* __restrict__ W2,
                 const float* __restrict__ bias,
                 float* __restrict__ out_plain)
{
    __shared__ float As[8][128];
    __shared__ float Bs[8][128];

    const int bn  = blockIdx.x;          // 0..7  (N/128)
    const int bm  = blockIdx.y;          // 0..31 (M/128)
    const int tid = threadIdx.x;
    const int tx  = tid & 15;            // 0..15
    const int ty  = tid >> 4;            // 0..15

    const float* W = W0;
    if (MODE == 0) { W = (blockIdx.z == 0) ? W0 : (blockIdx.z == 1) ? W1 : W2; }

    float acc[8][8];
    #pragma unroll
    for (int i = 0; i < 8; i++)
        #pragma unroll
        for (int j = 0; j < 8; j++) acc[i][j] = 0.f;

    const int a_m = tid >> 1;            // row within tile for A load
    const int a_k = (tid & 1) * 4;       // k offset (0 or 4)
    const int b_k = tid >> 5;            // 0..7
    const int b_n = (tid & 31) * 4;      // 0..124

    for (int k0 = 0; k0 < Dq; k0 += 8) {
        float4 a4 = *(const float4*)&A[(size_t)(bm*128 + a_m)*Dq + k0 + a_k];
        As[a_k+0][a_m] = a4.x; As[a_k+1][a_m] = a4.y;
        As[a_k+2][a_m] = a4.z; As[a_k+3][a_m] = a4.w;
        *(float4*)&Bs[b_k][b_n] =
            *(const float4*)&W[(size_t)(k0 + b_k)*Dq + bn*128 + b_n];
        __syncthreads();

        #pragma unroll
        for (int kk = 0; kk < 8; kk++) {
            float a[8], b[8];
            *(float4*)&a[0] = *(float4*)&As[kk][ty*8];
            *(float4*)&a[4] = *(float4*)&As[kk][ty*8+4];
            *(float4*)&b[0] = *(float4*)&Bs[kk][tx*8];
            *(float4*)&b[4] = *(float4*)&Bs[kk][tx*8+4];
            #pragma unroll
            for (int i = 0; i < 8; i++)
                #pragma unroll
                for (int j = 0; j < 8; j++)
                    acc[i][j] = fmaf(a[i], b[j], acc[i][j]);
        }
        __syncthreads();
    }

    if (MODE == 0) {
        // scatter into [B,H,S,DH]
        float* dst = (blockIdx.z == 0) ? g_q : (blockIdx.z == 1) ? g_k : g_v;
        #pragma unroll
        for (int i = 0; i < 8; i++) {
            int t = bm*128 + ty*8 + i;       // token row 0..4095
            int b = t >> 11, s = t & 2047;
            #pragma unroll
            for (int j = 0; j < 8; j += 4) {
                int c  = bn*128 + tx*8 + j;  // col 0..1023
                int h  = c >> 6, dh = c & 63;
                float4 v = make_float4(acc[i][j], acc[i][j+1], acc[i][j+2], acc[i][j+3]);
                *(float4*)&dst[(size_t)((b*Hq + h)*Sq + s)*DHq + dh] = v;
            }
        }
    } else {
        #pragma unroll
        for (int i = 0; i < 8; i++) {
            int t = bm*128 + ty*8 + i;
            #pragma unroll
            for (int j = 0; j < 8; j += 4) {
                int c = bn*128 + tx*8 + j;
                float4 v = make_float4(acc[i][j]   + bias[c],
                                       acc[i][j+1] + bias[c+1],
                                       acc[i][j+2] + bias[c+2],
                                       acc[i][j+3] + bias[c+3]);
                *(float4*)&out_plain[(size_t)t*Dq + c] = v;
            }
        }
    }
}

// ---------------------------------------------------------------------------
// Flash attention (causal). One thread = one query row. 128 query rows/block.
// K/V tiles of 64 keys in smem; online softmax in 16-key chunks.
// ---------------------------------------------------------------------------
__global__ __launch_bounds__(128)
void attn_kernel()
{
    __shared__ float Ks[64*64];
    __shared__ float Vs[64*64];

    const int bh  = blockIdx.y;                 // 0..31
    const int q0  = blockIdx.x * 128;
    const int tid = threadIdx.x;
    const int qi  = q0 + tid;                   // this thread's query row

    const float* Qb = g_q + (size_t)bh * Sq * DHq;
    const float* Kb = g_k + (size_t)bh * Sq * DHq;
    const float* Vb = g_v + (size_t)bh * Sq * DHq;

    float qv[64];
    #pragma unroll
    for (int d = 0; d < 64; d += 4)
        *(float4*)&qv[d] = *(const float4*)&Qb[(size_t)qi*DHq + d];

    float acc[64];
    #pragma unroll
    for (int d = 0; d < 64; d++) acc[d] = 0.f;
    float m = -CUDART_INF_F, l = 0.f;

    const float scale = 0.125f;                 // 1/sqrt(64)

    for (int kj0 = 0; kj0 <= q0 + 127; kj0 += 64) {
        // cooperative coalesced K/V tile load (64 rows x 64 cols)
        #pragma unroll
        for (int e = 0; e < 8; e++) {
            int idx = e*512 + tid*4;
            *(float4*)&Ks[idx] = *(const float4*)&Kb[(size_t)kj0*DHq + idx];
            *(float4*)&Vs[idx] = *(const float4*)&Vb[(size_t)kj0*DHq + idx];
        }
        __syncthreads();

        #pragma unroll 1
        for (int c = 0; c < 64; c += 16) {
            if (kj0 + c > qi) break;            // whole chunk masked for this row
            float s[16];
            #pragma unroll
            for (int jj = 0; jj < 16; jj++) {
                const float* kr = &Ks[(c+jj)*64];
                float sum = 0.f;
                #pragma unroll
                for (int d = 0; d < 64; d += 4) {
                    float4 k4 = *(const float4*)&kr[d];
                    sum = fmaf(qv[d+0], k4.x, sum);
                    sum = fmaf(qv[d+1], k4.y, sum);
                    sum = fmaf(qv[d+2], k4.z, sum);
                    sum = fmaf(qv[d+3], k4.w, sum);
                }
                s[jj] = (kj0 + c + jj > qi) ? -CUDART_INF_F : sum * scale;
            }
            float cmax = s[0];
            #pragma unroll
            for (int jj = 1; jj < 16; jj++) cmax = fmaxf(cmax, s[jj]);
            float m_new = fmaxf(m, cmax);
            float corr  = __expf(m - m_new);    // m=-inf -> 0, safe
            l *= corr;
            #pragma unroll
            for (int d = 0; d < 64; d++) acc[d] *= corr;

            float psum = 0.f;
            #pragma unroll
            for (int jj = 0; jj < 16; jj++) {
                float p = __expf(s[jj] - m_new);  // masked -> exp(-inf)=0
                psum += p;
                const float* vr = &Vs[(c+jj)*64];
                #pragma unroll
                for (int d = 0; d < 64; d += 4) {
                    float4 v4 = *(const float4*)&vr[d];
                    acc[d+0] = fmaf(p, v4.x, acc[d+0]);
                    acc[d+1] = fmaf(p, v4.y, acc[d+1]);
                    acc[d+2] = fmaf(p, v4.z, acc[d+2]);
                    acc[d+3] = fmaf(p, v4.w, acc[d+3]);
                }
            }
            l += psum;
            m  = m_new;
        }
        __syncthreads();
    }

    const float inv = 1.0f / l;
    const int b = bh >> 4, h = bh & 15;
    float* outp = g_ctx + ((size_t)(b*Sq + qi))*Dq + h*DHq;
    #pragma unroll
    for (int d = 0; d < 64; d += 4) {
        float4 v = make_float4(acc[d]*inv, acc[d+1]*inv, acc[d+2]*inv, acc[d+3]*inv);
        *(float4*)&outp[d] = v;
    }
}

// ---------------------------------------------------------------------------
// Launch
// ---------------------------------------------------------------------------
extern "C" void kernel_launch(void* const* d_in, const int* in_sizes, int n_in,
                              void* d_out, int out_size)
{
    const float* x  = (const float*)d_in[0];
    const float* Wq = (const float*)d_in[1];
    const float* Wk = (const float*)d_in[2];
    const float* Wv = (const float*)d_in[3];
    const float* Wo = (const float*)d_in[4];
    const float* bo = (const float*)d_in[5];
    float* out = (float*)d_out;

    // QKV projections (z = 0/1/2 selects Wq/Wk/Wv)
    gemm_kernel<0><<<dim3(Dq/128, Mq/128, 3), 256>>>(x, Wq, Wk, Wv, nullptr, nullptr);

    // causal flash attention -> g_ctx
    attn_kernel<<<dim3(Sq/128, BHq), 128>>>();

    // output projection + bias -> d_out  (A = g_ctx via symbol)
    // get raw pointer to g_ctx through a device-symbol trampoline:
    // pass it as A by letting the kernel read the global directly is not
    // possible for the shared template, so resolve the symbol address here.
    static float* ctx_ptr = nullptr;
    if (!ctx_ptr) cudaGetSymbolAddress((void**)&ctx_ptr, g_ctx);
    gemm_kernel<1><<<dim3(Dq/128, Mq/128, 1), 256>>>(ctx_ptr, Wo, nullptr, nullptr, bo, out);
}

// round 3
// speedup vs baseline: 1.4676x; 1.4676x over previous
#include <cuda_runtime.h>
#include <math_constants.h>
#include <cstdint>

// Shapes (fixed by the problem)
#define Bq   2
#define Sq   2048
#define Dq   1024
#define Hq   16
#define DHq  64
#define BHq  (Bq*Hq)          // 32
#define Mq   (Bq*Sq)          // 4096

#define PADK 36               // smem row stride (floats) for 32-float rows

// Scratch
__device__ float g_q  [BHq * Sq * DHq];
__device__ float g_k  [BHq * Sq * DHq];
__device__ float g_v  [BHq * Sq * DHq];
__device__ float g_ctx[Bq * Sq * Dq];
__device__ float g_xr [Mq * Dq];         // tf32-rounded x
__device__ float g_wt [4 * Dq * Dq];     // tf32-rounded W^T : [N,K] K-major

// ---------------------------------------------------------------------------
// helpers
// ---------------------------------------------------------------------------
__device__ __forceinline__ float rna_tf32(float x) {
    float y;
    asm("cvt.rna.tf32.f32 %0, %1;" : "=f"(y) : "f"(x));
    return y;
}
__device__ __forceinline__ uint32_t smem_u32(const void* p) {
    uint32_t a;
    asm("{ .reg .u64 t; cvta.to.shared.u64 t, %1; cvt.u32.u64 %0, t; }"
        : "=r"(a) : "l"(p));
    return a;
}
#define CP_ASYNC16(dst, src) \
    asm volatile("cp.async.ca.shared.global [%0], [%1], 16;" \
                 :: "r"(dst), "l"(src) : "memory")
#define CP_COMMIT() asm volatile("cp.async.commit_group;" ::: "memory")
#define CP_WAIT(n)  asm volatile("cp.async.wait_group %0;" :: "n"(n) : "memory")

__device__ __forceinline__ void mma_tf32(float* d, uint32_t a0, uint32_t a1,
                                         uint32_t a2, uint32_t a3,
                                         uint32_t b0, uint32_t b1) {
    asm volatile(
        "mma.sync.aligned.m16n8k8.row.col.f32.tf32.tf32.f32 "
        "{%0,%1,%2,%3}, {%4,%5,%6,%7}, {%8,%9}, {%0,%1,%2,%3};"
        : "+f"(d[0]), "+f"(d[1]), "+f"(d[2]), "+f"(d[3])
        : "r"(a0), "r"(a1), "r"(a2), "r"(a3), "r"(b0), "r"(b1));
}

// ---------------------------------------------------------------------------
// prep: round x to tf32 grid -> g_xr
// ---------------------------------------------------------------------------
__global__ __launch_bounds__(256)
void prep_x_kernel(const float* __restrict__ x)
{
    int i = blockIdx.x * 256 + threadIdx.x;     // float4 index
    float4 v = ((const float4*)x)[i];
    v.x = rna_tf32(v.x); v.y = rna_tf32(v.y);
    v.z = rna_tf32(v.z); v.w = rna_tf32(v.w);
    ((float4*)g_xr)[i] = v;
}

// ---------------------------------------------------------------------------
// prep: g_wt[z][n][k] = rna(W_z[k][n])
// ---------------------------------------------------------------------------
__global__ __launch_bounds__(256)
void prep_wt_kernel(const float* __restrict__ Wq, const float* __restrict__ Wk,
                    const float* __restrict__ Wv, const float* __restrict__ Wo)
{
    __shared__ float t[32][33];
    const int z = blockIdx.z;
    const float* W = (z == 0) ? Wq : (z == 1) ? Wk : (z == 2) ? Wv : Wo;
    const int k0 = blockIdx.x * 32, n0 = blockIdx.y * 32;
    const int tx = threadIdx.x, ty = threadIdx.y;   // 32 x 8
    #pragma unroll
    for (int i = 0; i < 32; i += 8)
        t[ty + i][tx] = W[(size_t)(k0 + ty + i) * Dq + n0 + tx];
    __syncthreads();
    float* dst = g_wt + (size_t)z * Dq * Dq;
    #pragma unroll
    for (int i = 0; i < 32; i += 8)
        dst[(size_t)(n0 + ty + i) * Dq + k0 + tx] = rna_tf32(t[tx][ty + i]);
}

// ---------------------------------------------------------------------------
// tf32 mma.sync GEMM: C[128x128/CTA] = A[4096x1024] * W[1024x1024]
// 256 threads = 8 warps, warp grid 4(M) x 2(N), warp tile 32x64.
// cp.async double-buffered K-chunks of 32.
// MODE 0: scatter into g_q/g_k/g_v ([B,H,S,DH]) per blockIdx.z
// MODE 1: d_out = C + bias
// ---------------------------------------------------------------------------
#define GEMM_SMEM (2 * 2 * 128 * PADK * 4)      // 73728 bytes

template <int MODE>
__global__ __launch_bounds__(256)
void gemm_mma(const float* __restrict__ A,
              const float* __restrict__ bias,
              float* __restrict__ out)
{
    extern __shared__ float sm[];
    // layout: stage0 A(128*PADK) | stage0 B | stage1 A | stage1 B

    const int tid  = threadIdx.x;
    const int wid  = tid >> 5;
    const int lane = tid & 31;
    const int wm   = wid & 3;                   // warp row (M)
    const int wn   = wid >> 2;                  // warp col (N)
    const int bn   = blockIdx.x;                // 0..7
    const int bm   = blockIdx.y;                // 0..31
    const int g    = lane >> 2;                 // 0..7
    const int tkc  = lane & 3;                  // 0..3

    const int z = (MODE == 0) ? blockIdx.z : 3;
    const float* Ab = A    + (size_t)(bm * 128) * Dq;
    const float* Bb = g_wt + (size_t)z * Dq * Dq + (size_t)(bn * 128) * Dq;

    const uint32_t sm_u32 = smem_u32(sm);
    const int stage_f = 2 * 128 * PADK;         // floats per stage

    // per-thread load slots: 4 rows of A + 4 rows of B per stage
    const int lr  = tid >> 1;                   // 0..127 base row pairs
    // simpler mapping: e = it*256+tid -> row=e>>3, c4=(e&7)*4

    float acc[2][8][4];
    #pragma unroll
    for (int i = 0; i < 2; i++)
        #pragma unroll
        for (int j = 0; j < 8; j++)
            #pragma unroll
            for (int l = 0; l < 4; l++) acc[i][j][l] = 0.f;
    (void)lr;

    // ---- pipeline ----
    auto issue_loads = [&](int stage, int k0) {
        uint32_t as = sm_u32 + (uint32_t)(stage * stage_f) * 4u;
        uint32_t bs = as + (uint32_t)(128 * PADK) * 4u;
        #pragma unroll
        for (int it = 0; it < 4; it++) {
            int e  = it * 256 + tid;
            int r  = e >> 3;
            int c4 = (e & 7) * 4;
            uint32_t off = (uint32_t)(r * PADK + c4) * 4u;
            CP_ASYNC16(as + off, Ab + (size_t)r * Dq + k0 + c4);
            CP_ASYNC16(bs + off, Bb + (size_t)r * Dq + k0 + c4);
        }
        CP_COMMIT();
    };

    issue_loads(0, 0);

    #pragma unroll 1
    for (int t = 0; t < 32; t++) {
        if (t + 1 < 32) { issue_loads((t + 1) & 1, (t + 1) * 32); CP_WAIT(1); }
        else            { CP_WAIT(0); }
        __syncthreads();

        const float* As = sm + (t & 1) * stage_f;
        const float* Bs = As + 128 * PADK;

        #pragma unroll
        for (int ks = 0; ks < 4; ks++) {
            const int kb = ks * 8 + tkc;
            uint32_t bf[8][2];
            #pragma unroll
            for (int nf = 0; nf < 8; nf++) {
                const float* bp = &Bs[(wn * 64 + nf * 8 + g) * PADK + kb];
                bf[nf][0] = __float_as_uint(bp[0]);
                bf[nf][1] = __float_as_uint(bp[4]);
            }
            #pragma unroll
            for (int mf = 0; mf < 2; mf++) {
                const float* ap = &As[(wm * 32 + mf * 16 + g) * PADK + kb];
                uint32_t a0 = __float_as_uint(ap[0]);
                uint32_t a1 = __float_as_uint(ap[8 * PADK]);
                uint32_t a2 = __float_as_uint(ap[4]);
                uint32_t a3 = __float_as_uint(ap[8 * PADK + 4]);
                #pragma unroll
                for (int nf = 0; nf < 8; nf++)
                    mma_tf32(acc[mf][nf], a0, a1, a2, a3, bf[nf][0], bf[nf][1]);
            }
        }
        __syncthreads();
    }

    // ---- epilogue ----
    #pragma unroll
    for (int mf = 0; mf < 2; mf++) {
        const int r0 = bm * 128 + wm * 32 + mf * 16 + g;
        #pragma unroll
        for (int nf = 0; nf < 8; nf++) {
            const int c = bn * 128 + wn * 64 + nf * 8 + tkc * 2;
            if (MODE == 0) {
                float* dst = (blockIdx.z == 0) ? g_q : (blockIdx.z == 1) ? g_k : g_v;
                const int h = c >> 6, dh = c & 63;
                {
                    const int b = r0 >> 11, s = r0 & 2047;
                    float2 v = make_float2(acc[mf][nf][0], acc[mf][nf][1]);
                    *(float2*)&dst[(size_t)((b * Hq + h) * Sq + s) * DHq + dh] = v;
                }
                {
                    const int r1 = r0 + 8;
                    const int b = r1 >> 11, s = r1 & 2047;
                    float2 v = make_float2(acc[mf][nf][2], acc[mf][nf][3]);
                    *(float2*)&dst[(size_t)((b * Hq + h) * Sq + s) * DHq + dh] = v;
                }
            } else {
                float2 bv = *(const float2*)&bias[c];
                float2 v0 = make_float2(acc[mf][nf][0] + bv.x, acc[mf][nf][1] + bv.y);
                float2 v1 = make_float2(acc[mf][nf][2] + bv.x, acc[mf][nf][3] + bv.y);
                *(float2*)&out[(size_t)r0 * Dq + c]       = v0;
                *(float2*)&out[(size_t)(r0 + 8) * Dq + c] = v1;
            }
        }
    }
}

// ---------------------------------------------------------------------------
// Flash attention (causal), fp32 — unchanged except tf32-rounding ctx store.
// ---------------------------------------------------------------------------
__global__ __launch_bounds__(128)
void attn_kernel()
{
    __shared__ float Ks[64*64];
    __shared__ float Vs[64*64];

    const int bh  = blockIdx.y;
    const int q0  = blockIdx.x * 128;
    const int tid = threadIdx.x;
    const int qi  = q0 + tid;

    const float* Qb = g_q + (size_t)bh * Sq * DHq;
    const float* Kb = g_k + (size_t)bh * Sq * DHq;
    const float* Vb = g_v + (size_t)bh * Sq * DHq;

    float qv[64];
    #pragma unroll
    for (int d = 0; d < 64; d += 4)
        *(float4*)&qv[d] = *(const float4*)&Qb[(size_t)qi*DHq + d];

    float acc[64];
    #pragma unroll
    for (int d = 0; d < 64; d++) acc[d] = 0.f;
    float m = -CUDART_INF_F, l = 0.f;
    const float scale = 0.125f;

    for (int kj0 = 0; kj0 <= q0 + 127; kj0 += 64) {
        #pragma unroll
        for (int e = 0; e < 8; e++) {
            int idx = e*512 + tid*4;
            *(float4*)&Ks[idx] = *(const float4*)&Kb[(size_t)kj0*DHq + idx];
            *(float4*)&Vs[idx] = *(const float4*)&Vb[(size_t)kj0*DHq + idx];
        }
        __syncthreads();

        #pragma unroll 1
        for (int c = 0; c < 64; c += 16) {
            if (kj0 + c > qi) break;
            float s[16];
            #pragma unroll
            for (int jj = 0; jj < 16; jj++) {
                const float* kr = &Ks[(c+jj)*64];
                float sum = 0.f;
                #pragma unroll
                for (int d = 0; d < 64; d += 4) {
                    float4 k4 = *(const float4*)&kr[d];
                    sum = fmaf(qv[d+0], k4.x, sum);
                    sum = fmaf(qv[d+1], k4.y, sum);
                    sum = fmaf(qv[d+2], k4.z, sum);
                    sum = fmaf(qv[d+3], k4.w, sum);
                }
                s[jj] = (kj0 + c + jj > qi) ? -CUDART_INF_F : sum * scale;
            }
            float cmax = s[0];
            #pragma unroll
            for (int jj = 1; jj < 16; jj++) cmax = fmaxf(cmax, s[jj]);
            float m_new = fmaxf(m, cmax);
            float corr  = __expf(m - m_new);
            l *= corr;
            #pragma unroll
            for (int d = 0; d < 64; d++) acc[d] *= corr;

            float psum = 0.f;
            #pragma unroll
            for (int jj = 0; jj < 16; jj++) {
                float p = __expf(s[jj] - m_new);
                psum += p;
                const float* vr = &Vs[(c+jj)*64];
                #pragma unroll
                for (int d = 0; d < 64; d += 4) {
                    float4 v4 = *(const float4*)&vr[d];
                    acc[d+0] = fmaf(p, v4.x, acc[d+0]);
                    acc[d+1] = fmaf(p, v4.y, acc[d+1]);
                    acc[d+2] = fmaf(p, v4.z, acc[d+2]);
                    acc[d+3] = fmaf(p, v4.w, acc[d+3]);
                }
            }
            l += psum;
            m  = m_new;
        }
        __syncthreads();
    }

    const float inv = 1.0f / l;
    const int b = bh >> 4, h = bh & 15;
    float* outp = g_ctx + ((size_t)(b*Sq + qi))*Dq + h*DHq;
    #pragma unroll
    for (int d = 0; d < 64; d += 4) {
        float4 v = make_float4(rna_tf32(acc[d]*inv),   rna_tf32(acc[d+1]*inv),
                               rna_tf32(acc[d+2]*inv), rna_tf32(acc[d+3]*inv));
        *(float4*)&outp[d] = v;
    }
}

// ---------------------------------------------------------------------------
// Launch
// ---------------------------------------------------------------------------
extern "C" void kernel_launch(void* const* d_in, const int* in_sizes, int n_in,
                              void* d_out, int out_size)
{
    const float* x  = (const float*)d_in[0];
    const float* Wq = (const float*)d_in[1];
    const float* Wk = (const float*)d_in[2];
    const float* Wv = (const float*)d_in[3];
    const float* Wo = (const float*)d_in[4];
    const float* bo = (const float*)d_in[5];
    float* out = (float*)d_out;

    static float* ctx_ptr = nullptr;
    static float* xr_ptr  = nullptr;
    if (!ctx_ptr) cudaGetSymbolAddress((void**)&ctx_ptr, g_ctx);
    if (!xr_ptr)  cudaGetSymbolAddress((void**)&xr_ptr,  g_xr);

    cudaFuncSetAttribute(gemm_mma<0>, cudaFuncAttributeMaxDynamicSharedMemorySize, GEMM_SMEM);
    cudaFuncSetAttribute(gemm_mma<1>, cudaFuncAttributeMaxDynamicSharedMemorySize, GEMM_SMEM);

    // prep: tf32-round x and transposed weights
    prep_x_kernel<<<Mq * Dq / 4 / 256, 256>>>(x);
    prep_wt_kernel<<<dim3(Dq/32, Dq/32, 4), dim3(32, 8)>>>(Wq, Wk, Wv, Wo);

    // QKV projections on tensor cores (tf32 mma.sync)
    gemm_mma<0><<<dim3(Dq/128, Mq/128, 3), 256, GEMM_SMEM>>>(xr_ptr, nullptr, nullptr);

    // causal flash attention (fp32) -> g_ctx (tf32-rounded)
    attn_kernel<<<dim3(Sq/128, BHq), 128>>>();

    // output projection + bias -> d_out
    gemm_mma<1><<<dim3(Dq/128, Mq/128, 1), 256, GEMM_SMEM>>>(ctx_ptr, bo, out);
}

// round 4
// speedup vs baseline: 4.0972x; 2.7918x over previous
#include <cuda_runtime.h>
#include <math_constants.h>
#include <cstdint>

// Shapes (fixed by the problem)
#define Bq   2
#define Sq   2048
#define Dq   1024
#define Hq   16
#define DHq  64
#define BHq  (Bq*Hq)          // 32
#define Mq   (Bq*Sq)          // 4096

#define PADK 36               // smem row stride (floats) for 32-float rows (GEMM)
#define APAD 68               // smem row stride (floats) for 64-float rows (attn)

// Scratch
__device__ float g_q  [BHq * Sq * DHq];        // [b,h,s,dh]
__device__ float g_k  [BHq * Sq * DHq];        // [b,h,s,dh]
__device__ float g_vt [BHq * DHq * Sq];        // [b,h,dh,s]  (transposed V)
__device__ float g_ctx[Bq * Sq * Dq];
__device__ float g_xr [Mq * Dq];               // tf32-rounded x
__device__ float g_wt [4 * Dq * Dq];           // tf32-rounded W^T : [N,K] K-major

// ---------------------------------------------------------------------------
// helpers
// ---------------------------------------------------------------------------
__device__ __forceinline__ float rna_tf32(float x) {
    float y;
    asm("cvt.rna.tf32.f32 %0, %1;" : "=f"(y) : "f"(x));
    return y;
}
__device__ __forceinline__ uint32_t smem_u32(const void* p) {
    uint32_t a;
    asm("{ .reg .u64 t; cvta.to.shared.u64 t, %1; cvt.u32.u64 %0, t; }"
        : "=r"(a) : "l"(p));
    return a;
}
#define CP_ASYNC16(dst, src) \
    asm volatile("cp.async.ca.shared.global [%0], [%1], 16;" \
                 :: "r"(dst), "l"(src) : "memory")
#define CP_COMMIT() asm volatile("cp.async.commit_group;" ::: "memory")
#define CP_WAIT(n)  asm volatile("cp.async.wait_group %0;" :: "n"(n) : "memory")

__device__ __forceinline__ void mma_tf32(float* d, uint32_t a0, uint32_t a1,
                                         uint32_t a2, uint32_t a3,
                                         uint32_t b0, uint32_t b1) {
    asm volatile(
        "mma.sync.aligned.m16n8k8.row.col.f32.tf32.tf32.f32 "
        "{%0,%1,%2,%3}, {%4,%5,%6,%7}, {%8,%9}, {%0,%1,%2,%3};"
        : "+f"(d[0]), "+f"(d[1]), "+f"(d[2]), "+f"(d[3])
        : "r"(a0), "r"(a1), "r"(a2), "r"(a3), "r"(b0), "r"(b1));
}

// ---------------------------------------------------------------------------
// prep kernels
// ---------------------------------------------------------------------------
__global__ __launch_bounds__(256)
void prep_x_kernel(const float* __restrict__ x)
{
    int i = blockIdx.x * 256 + threadIdx.x;
    float4 v = ((const float4*)x)[i];
    v.x = rna_tf32(v.x); v.y = rna_tf32(v.y);
    v.z = rna_tf32(v.z); v.w = rna_tf32(v.w);
    ((float4*)g_xr)[i] = v;
}

__global__ __launch_bounds__(256)
void prep_wt_kernel(const float* __restrict__ Wq, const float* __restrict__ Wk,
                    const float* __restrict__ Wv, const float* __restrict__ Wo)
{
    __shared__ float t[32][33];
    const int z = blockIdx.z;
    const float* W = (z == 0) ? Wq : (z == 1) ? Wk : (z == 2) ? Wv : Wo;
    const int k0 = blockIdx.x * 32, n0 = blockIdx.y * 32;
    const int tx = threadIdx.x, ty = threadIdx.y;
    #pragma unroll
    for (int i = 0; i < 32; i += 8)
        t[ty + i][tx] = W[(size_t)(k0 + ty + i) * Dq + n0 + tx];
    __syncthreads();
    float* dst = g_wt + (size_t)z * Dq * Dq;
    #pragma unroll
    for (int i = 0; i < 32; i += 8)
        dst[(size_t)(n0 + ty + i) * Dq + k0 + tx] = rna_tf32(t[tx][ty + i]);
}

// ---------------------------------------------------------------------------
// tf32 mma.sync GEMM (unchanged core from round 3)
// MODE 0: z=0 -> g_q, z=1 -> g_k (both rounded), z=2 -> g_vt transposed+rounded
// MODE 1: d_out = C + bias
// ---------------------------------------------------------------------------
#define GEMM_SMEM (2 * 2 * 128 * PADK * 4)

template <int MODE>
__global__ __launch_bounds__(256)
void gemm_mma(const float* __restrict__ A,
              const float* __restrict__ bias,
              float* __restrict__ out)
{
    extern __shared__ float sm[];
    const int tid  = threadIdx.x;
    const int wid  = tid >> 5;
    const int lane = tid & 31;
    const int wm   = wid & 3;
    const int wn   = wid >> 2;
    const int bn   = blockIdx.x;
    const int bm   = blockIdx.y;
    const int g    = lane >> 2;
    const int tkc  = lane & 3;

    const int z = (MODE == 0) ? blockIdx.z : 3;
    const float* Ab = A    + (size_t)(bm * 128) * Dq;
    const float* Bb = g_wt + (size_t)z * Dq * Dq + (size_t)(bn * 128) * Dq;

    const uint32_t sm_u32 = smem_u32(sm);
    const int stage_f = 2 * 128 * PADK;

    float acc[2][8][4];
    #pragma unroll
    for (int i = 0; i < 2; i++)
        #pragma unroll
        for (int j = 0; j < 8; j++)
            #pragma unroll
            for (int l = 0; l < 4; l++) acc[i][j][l] = 0.f;

    auto issue_loads = [&](int stage, int k0) {
        uint32_t as = sm_u32 + (uint32_t)(stage * stage_f) * 4u;
        uint32_t bs = as + (uint32_t)(128 * PADK) * 4u;
        #pragma unroll
        for (int it = 0; it < 4; it++) {
            int e  = it * 256 + tid;
            int r  = e >> 3;
            int c4 = (e & 7) * 4;
            uint32_t off = (uint32_t)(r * PADK + c4) * 4u;
            CP_ASYNC16(as + off, Ab + (size_t)r * Dq + k0 + c4);
            CP_ASYNC16(bs + off, Bb + (size_t)r * Dq + k0 + c4);
        }
        CP_COMMIT();
    };

    issue_loads(0, 0);

    #pragma unroll 1
    for (int t = 0; t < 32; t++) {
        if (t + 1 < 32) { issue_loads((t + 1) & 1, (t + 1) * 32); CP_WAIT(1); }
        else            { CP_WAIT(0); }
        __syncthreads();

        const float* As = sm + (t & 1) * stage_f;
        const float* Bs = As + 128 * PADK;

        #pragma unroll
        for (int ks = 0; ks < 4; ks++) {
            const int kb = ks * 8 + tkc;
            uint32_t bf[8][2];
            #pragma unroll
            for (int nf = 0; nf < 8; nf++) {
                const float* bp = &Bs[(wn * 64 + nf * 8 + g) * PADK + kb];
                bf[nf][0] = __float_as_uint(bp[0]);
                bf[nf][1] = __float_as_uint(bp[4]);
            }
            #pragma unroll
            for (int mf = 0; mf < 2; mf++) {
                const float* ap = &As[(wm * 32 + mf * 16 + g) * PADK + kb];
                uint32_t a0 = __float_as_uint(ap[0]);
                uint32_t a1 = __float_as_uint(ap[8 * PADK]);
                uint32_t a2 = __float_as_uint(ap[4]);
                uint32_t a3 = __float_as_uint(ap[8 * PADK + 4]);
                #pragma unroll
                for (int nf = 0; nf < 8; nf++)
                    mma_tf32(acc[mf][nf], a0, a1, a2, a3, bf[nf][0], bf[nf][1]);
            }
        }
        __syncthreads();
    }

    #pragma unroll
    for (int mf = 0; mf < 2; mf++) {
        const int r0 = bm * 128 + wm * 32 + mf * 16 + g;
        #pragma unroll
        for (int nf = 0; nf < 8; nf++) {
            const int c = bn * 128 + wn * 64 + nf * 8 + tkc * 2;
            if (MODE == 0) {
                const int h = c >> 6, dh = c & 63;
                if (blockIdx.z == 2) {
                    // V: transposed [b,h,dh,s] + tf32 rounding
                    #pragma unroll
                    for (int rr = 0; rr < 2; rr++) {
                        const int r = r0 + rr * 8;
                        const int b = r >> 11, s = r & 2047;
                        float* base = g_vt + ((size_t)((b * Hq + h) * DHq + dh)) * Sq + s;
                        base[0]  = rna_tf32(acc[mf][nf][rr * 2]);
                        base[Sq] = rna_tf32(acc[mf][nf][rr * 2 + 1]);
                    }
                } else {
                    float* dst = (blockIdx.z == 0) ? g_q : g_k;
                    #pragma unroll
                    for (int rr = 0; rr < 2; rr++) {
                        const int r = r0 + rr * 8;
                        const int b = r >> 11, s = r & 2047;
                        float2 v = make_float2(rna_tf32(acc[mf][nf][rr * 2]),
                                               rna_tf32(acc[mf][nf][rr * 2 + 1]));
                        *(float2*)&dst[(size_t)((b * Hq + h) * Sq + s) * DHq + dh] = v;
                    }
                }
            } else {
                float2 bv = *(const float2*)&bias[c];
                float2 v0 = make_float2(acc[mf][nf][0] + bv.x, acc[mf][nf][1] + bv.y);
                float2 v1 = make_float2(acc[mf][nf][2] + bv.x, acc[mf][nf][3] + bv.y);
                *(float2*)&out[(size_t)r0 * Dq + c]       = v0;
                *(float2*)&out[(size_t)(r0 + 8) * Dq + c] = v1;
            }
        }
    }
}

// ---------------------------------------------------------------------------
// Tensor-core flash attention (causal, tf32 mma.sync).
// CTA: 128 queries x one (b,h). 8 warps x 16 query rows. Key tiles of 64.
// ---------------------------------------------------------------------------
#define STG_F (64 * APAD)                       // floats per K or Vt buffer
#define ATT_SMEM ((4 * STG_F + 128 * APAD) * 4) // 104448 bytes

__global__ __launch_bounds__(256)
void attn_mma()
{
    extern __shared__ float sm[];
    const int tid  = threadIdx.x;
    const int wid  = tid >> 5;
    const int lane = tid & 31;
    const int g    = lane >> 2;
    const int t    = lane & 3;
    const int bh   = blockIdx.y;
    const int qblk = gridDim.x - 1 - blockIdx.x;   // long CTAs first
    const int q0   = qblk * 128;

    const float* Qg = g_q  + (size_t)bh * Sq * DHq;
    const float* Kg = g_k  + (size_t)bh * Sq * DHq;
    const float* Vt = g_vt + (size_t)bh * DHq * Sq;

    float* Pb = sm + 4 * STG_F;                 // 128 x APAD; Q staging then P
    const uint32_t sm_b = smem_u32(sm);

    // --- load Q tile (cooperative), extract per-warp fragments ---
    #pragma unroll
    for (int it = 0; it < 8; it++) {
        int e = it * 256 + tid;
        int r = e >> 4, c4 = (e & 15) * 4;
        *(float4*)&Pb[r * APAD + c4] =
            *(const float4*)&Qg[(size_t)(q0 + r) * DHq + c4];
    }
    __syncthreads();

    const int wq = wid * 16;
    uint32_t qf[8][4];
    #pragma unroll
    for (int kg = 0; kg < 8; kg++) {
        const float* qp = &Pb[(wq + g) * APAD + kg * 8 + t];
        qf[kg][0] = __float_as_uint(qp[0]);
        qf[kg][1] = __float_as_uint(qp[8 * APAD]);
        qf[kg][2] = __float_as_uint(qp[4]);
        qf[kg][3] = __float_as_uint(qp[8 * APAD + 4]);
    }

    float o[8][4];
    #pragma unroll
    for (int nf = 0; nf < 8; nf++)
        #pragma unroll
        for (int j = 0; j < 4; j++) o[nf][j] = 0.f;
    float m0 = -CUDART_INF_F, m1 = -CUDART_INF_F, l0 = 0.f, l1 = 0.f;

    const int qi0 = q0 + wq + g;
    const int qi1 = qi0 + 8;
    const int ntiles = qblk * 2 + 2;

    auto issue = [&](int st, int kj0) {
        uint32_t ks = sm_b + (uint32_t)(st * 2 * STG_F) * 4u;
        uint32_t vs = ks + (uint32_t)STG_F * 4u;
        #pragma unroll
        for (int it = 0; it < 4; it++) {
            int e = it * 256 + tid;
            int r = e >> 4, c4 = (e & 15) * 4;
            uint32_t off = (uint32_t)(r * APAD + c4) * 4u;
            CP_ASYNC16(ks + off, Kg + (size_t)(kj0 + r) * DHq + c4);
            CP_ASYNC16(vs + off, Vt + (size_t)r * Sq + kj0 + c4);
        }
        CP_COMMIT();
    };

    issue(0, 0);

    #pragma unroll 1
    for (int tt = 0; tt < ntiles; tt++) {
        const int kj0 = tt * 64;
        if (tt + 1 < ntiles) { issue((tt + 1) & 1, (tt + 1) * 64); CP_WAIT(1); }
        else                 { CP_WAIT(0); }
        __syncthreads();

        const float* Ks = sm + (tt & 1) * 2 * STG_F;
        const float* Vs = Ks + STG_F;

        // ---- S = Q K^T ----
        float s[8][4];
        #pragma unroll
        for (int nf = 0; nf < 8; nf++)
            #pragma unroll
            for (int j = 0; j < 4; j++) s[nf][j] = 0.f;

        #pragma unroll
        for (int kg = 0; kg < 8; kg++) {
            const int kb = kg * 8 + t;
            #pragma unroll
            for (int nf = 0; nf < 8; nf++) {
                const float* bp = &Ks[(nf * 8 + g) * APAD + kb];
                mma_tf32(s[nf], qf[kg][0], qf[kg][1], qf[kg][2], qf[kg][3],
                         __float_as_uint(bp[0]), __float_as_uint(bp[4]));
            }
        }

        // ---- scale + causal mask + online softmax ----
        const bool doMask = (kj0 >= q0);
        float mx0 = -CUDART_INF_F, mx1 = -CUDART_INF_F;
        #pragma unroll
        for (int nf = 0; nf < 8; nf++) {
            #pragma unroll
            for (int j = 0; j < 4; j++) {
                float v = s[nf][j] * 0.125f;
                if (doMask) {
                    int col = kj0 + nf * 8 + t * 2 + (j & 1);
                    int qi  = (j < 2) ? qi0 : qi1;
                    if (col > qi) v = -CUDART_INF_F;
                }
                s[nf][j] = v;
                if (j < 2) mx0 = fmaxf(mx0, v); else mx1 = fmaxf(mx1, v);
            }
        }
        mx0 = fmaxf(mx0, __shfl_xor_sync(0xffffffffu, mx0, 1));
        mx0 = fmaxf(mx0, __shfl_xor_sync(0xffffffffu, mx0, 2));
        mx1 = fmaxf(mx1, __shfl_xor_sync(0xffffffffu, mx1, 1));
        mx1 = fmaxf(mx1, __shfl_xor_sync(0xffffffffu, mx1, 2));

        const float mn0 = fmaxf(m0, mx0);
        const float mn1 = fmaxf(m1, mx1);
        const float c0  = __expf(m0 - mn0);
        const float c1  = __expf(m1 - mn1);
        l0 *= c0; l1 *= c1;
        #pragma unroll
        for (int nf = 0; nf < 8; nf++) {
            o[nf][0] *= c0; o[nf][1] *= c0;
            o[nf][2] *= c1; o[nf][3] *= c1;
        }
        float sum0 = 0.f, sum1 = 0.f;
        #pragma unroll
        for (int nf = 0; nf < 8; nf++) {
            #pragma unroll
            for (int j = 0; j < 4; j++) {
                float p = __expf(s[nf][j] - ((j < 2) ? mn0 : mn1));
                p = rna_tf32(p);
                s[nf][j] = p;
                if (j < 2) sum0 += p; else sum1 += p;
            }
        }
        sum0 += __shfl_xor_sync(0xffffffffu, sum0, 1);
        sum0 += __shfl_xor_sync(0xffffffffu, sum0, 2);
        sum1 += __shfl_xor_sync(0xffffffffu, sum1, 1);
        sum1 += __shfl_xor_sync(0xffffffffu, sum1, 2);
        l0 += sum0; l1 += sum1;
        m0 = mn0;   m1 = mn1;

        // ---- P -> smem (per-warp region), C-layout -> A-layout ----
        float* Pw = Pb + wq * APAD;
        #pragma unroll
        for (int nf = 0; nf < 8; nf++) {
            *(float2*)&Pw[g * APAD + nf * 8 + t * 2]       = make_float2(s[nf][0], s[nf][1]);
            *(float2*)&Pw[(g + 8) * APAD + nf * 8 + t * 2] = make_float2(s[nf][2], s[nf][3]);
        }
        __syncwarp();

        // ---- O += P V ----
        #pragma unroll
        for (int kg = 0; kg < 8; kg++) {
            const int kb = kg * 8 + t;
            const float* pp = &Pw[g * APAD + kb];
            uint32_t a0 = __float_as_uint(pp[0]);
            uint32_t a1 = __float_as_uint(pp[8 * APAD]);
            uint32_t a2 = __float_as_uint(pp[4]);
            uint32_t a3 = __float_as_uint(pp[8 * APAD + 4]);
            #pragma unroll
            for (int nf = 0; nf < 8; nf++) {
                const float* bp = &Vs[(nf * 8 + g) * APAD + kb];
                mma_tf32(o[nf], a0, a1, a2, a3,
                         __float_as_uint(bp[0]), __float_as_uint(bp[4]));
            }
        }
        __syncthreads();   // stage buffer reuse safety
    }

    // ---- epilogue: normalize, tf32-round, store to g_ctx ----
    const float inv0 = 1.f / l0;
    const float inv1 = 1.f / l1;
    const int b = bh >> 4, h = bh & 15;
    #pragma unroll
    for (int nf = 0; nf < 8; nf++) {
        const int c = h * 64 + nf * 8 + t * 2;
        float2 v0 = make_float2(rna_tf32(o[nf][0] * inv0), rna_tf32(o[nf][1] * inv0));
        float2 v1 = make_float2(rna_tf32(o[nf][2] * inv1), rna_tf32(o[nf][3] * inv1));
        *(float2*)&g_ctx[(size_t)(b * Sq + qi0) * Dq + c] = v0;
        *(float2*)&g_ctx[(size_t)(b * Sq + qi1) * Dq + c] = v1;
    }
}

// ---------------------------------------------------------------------------
// Launch
// ---------------------------------------------------------------------------
extern "C" void kernel_launch(void* const* d_in, const int* in_sizes, int n_in,
                              void* d_out, int out_size)
{
    const float* x  = (const float*)d_in[0];
    const float* Wq = (const float*)d_in[1];
    const float* Wk = (const float*)d_in[2];
    const float* Wv = (const float*)d_in[3];
    const float* Wo = (const float*)d_in[4];
    const float* bo = (const float*)d_in[5];
    float* out = (float*)d_out;

    static float* ctx_ptr = nullptr;
    static float* xr_ptr  = nullptr;
    if (!ctx_ptr) cudaGetSymbolAddress((void**)&ctx_ptr, g_ctx);
    if (!xr_ptr)  cudaGetSymbolAddress((void**)&xr_ptr,  g_xr);

    static bool attr_done = false;
    if (!attr_done) {
        cudaFuncSetAttribute(gemm_mma<0>, cudaFuncAttributeMaxDynamicSharedMemorySize, GEMM_SMEM);
        cudaFuncSetAttribute(gemm_mma<1>, cudaFuncAttributeMaxDynamicSharedMemorySize, GEMM_SMEM);
        cudaFuncSetAttribute(attn_mma,    cudaFuncAttributeMaxDynamicSharedMemorySize, ATT_SMEM);
        attr_done = true;
    }

    prep_x_kernel<<<Mq * Dq / 4 / 256, 256>>>(x);
    prep_wt_kernel<<<dim3(Dq/32, Dq/32, 4), dim3(32, 8)>>>(Wq, Wk, Wv, Wo);

    // QKV projections (tf32 mma.sync); V written transposed
    gemm_mma<0><<<dim3(Dq/128, Mq/128, 3), 256, GEMM_SMEM>>>(xr_ptr, nullptr, nullptr);

    // tensor-core causal flash attention -> g_ctx
    attn_mma<<<dim3(Sq/128, BHq), 256, ATT_SMEM>>>();

    // output projection + bias -> d_out
    gemm_mma<1><<<dim3(Dq/128, Mq/128, 1), 256, GEMM_SMEM>>>(ctx_ptr, bo, out);
}